// round 1
// baseline (speedup 1.0000x reference)
#include <cuda_runtime.h>

// Problem constants (fixed shapes from reference setup_inputs):
//   left, right: [B, C, H, W] fp32 ; out: [B, C, D, H, W] fp32
#define BB 2
#define CC 32
#define HH 96
#define WW 320
#define DISP 48
#define W4 (WW / 4)          // 80 float4 per row
#define SR_PAD 48            // zero pad in front of right row so (w - d) never OOB
#define SR_LEN (SR_PAD + WW + 8)  // 376 floats, padded tail for q1 overread
#define NTHREADS 256

__global__ __launch_bounds__(NTHREADS)
void diffvolume_kernel(const float* __restrict__ left,
                       const float* __restrict__ right,
                       float* __restrict__ out) {
    __shared__ __align__(16) float sl[WW];
    __shared__ __align__(16) float sr[SR_LEN];

    const int row = blockIdx.x;              // row over (b*c, h) : bc*HH + h
    const float* lrow = left  + (size_t)row * WW;
    const float* rrow = right + (size_t)row * WW;
    const int t = threadIdx.x;

    // ---- stage the row pair into shared memory (all float4, coalesced) ----
    if (t < W4) {
        ((float4*)sl)[t] = ((const float4*)lrow)[t];
    } else if (t < 2 * W4) {
        ((float4*)(sr + SR_PAD))[t - W4] = ((const float4*)rrow)[t - W4];
    } else {
        int j = t - 2 * W4;                  // 96 spare threads zero the pads
        if (j < SR_PAD / 4) {
            ((float4*)sr)[j] = make_float4(0.f, 0.f, 0.f, 0.f);
        } else if (j < SR_PAD / 4 + 2) {
            ((float4*)(sr + SR_PAD + WW))[j - SR_PAD / 4] =
                make_float4(0.f, 0.f, 0.f, 0.f);
        }
    }
    __syncthreads();

    const int bc = row / HH;
    const int h  = row - bc * HH;

    float4* out4 = (float4*)out;
    // base index (float4 units) of out[bc, d=0, h, 0]
    const int ob = (bc * DISP * HH + h) * W4;
    const float4* sr4 = (const float4*)sr;
    const float4* sl4 = (const float4*)sl;

    // DISP*W4 = 3840 float4 outputs per block; 15 iterations per thread.
    for (int i = t; i < DISP * W4; i += NTHREADS) {
        const int d  = i / W4;               // disparity (warp-uniform except row seams)
        const int w4 = i - d * W4;
        const int w0 = w4 * 4;

        const int idx = w0 - d + SR_PAD;     // >= 1 always
        const int a   = idx >> 2;
        const int off = idx & 3;             // == (-d) & 3 : warp-near-uniform

        const float4 q0 = sr4[a];
        const float4 q1 = sr4[a + 1];
        float r0, r1, r2, r3;
        switch (off) {
            case 0:  r0 = q0.x; r1 = q0.y; r2 = q0.z; r3 = q0.w; break;
            case 1:  r0 = q0.y; r1 = q0.z; r2 = q0.w; r3 = q1.x; break;
            case 2:  r0 = q0.z; r1 = q0.w; r2 = q1.x; r3 = q1.y; break;
            default: r0 = q0.w; r1 = q1.x; r2 = q1.y; r3 = q1.z; break;
        }

        const float4 lv = sl4[w4];
        float4 o;
        o.x = (w0 + 0 >= d) ? lv.x - r0 : 0.f;
        o.y = (w0 + 1 >= d) ? lv.y - r1 : 0.f;
        o.z = (w0 + 2 >= d) ? lv.z - r2 : 0.f;
        o.w = (w0 + 3 >= d) ? lv.w - r3 : 0.f;

        out4[ob + d * (HH * W4) + w4] = o;
    }
}

extern "C" void kernel_launch(void* const* d_in, const int* in_sizes, int n_in,
                              void* d_out, int out_size) {
    const float* left  = (const float*)d_in[0];
    const float* right = (const float*)d_in[1];
    float* out = (float*)d_out;

    dim3 grid(BB * CC * HH);   // 6144 blocks, one per (b, c, h) row pair
    diffvolume_kernel<<<grid, NTHREADS>>>(left, right, out);
}

// round 2
// speedup vs baseline: 1.0056x; 1.0056x over previous
#include <cuda_runtime.h>

// left, right: [B, C, H, W] fp32 ; out: [B, C, D, H, W] fp32
#define BB 2
#define CC 32
#define HH 96
#define WW 320
#define DISP 48
#define W4 (WW / 4)            // 80 float4 per row
#define SR_PAD 48              // front zero pad so (w - d) never goes OOB
#define SR_LEN (SR_PAD + WW + 16)  // 384 floats
#define NTHREADS 320           // 80 w4-slots x 4 disparity groups
#define DG 12                  // disparities per group (48 / 4)

__global__ __launch_bounds__(NTHREADS)
void diffvolume_kernel(const float* __restrict__ left,
                       const float* __restrict__ right,
                       float* __restrict__ out) {
    __shared__ __align__(16) float sl[WW];
    __shared__ __align__(16) float sr[SR_LEN];

    const int row = blockIdx.x;              // bc*HH + h
    const float* lrow = left  + (size_t)row * WW;
    const float* rrow = right + (size_t)row * WW;
    const int t = threadIdx.x;

    // ---- stage the row pair into shared memory (float4, coalesced) ----
    if (t < W4) {
        ((float4*)sl)[t] = ((const float4*)lrow)[t];
    } else if (t < 2 * W4) {
        ((float4*)(sr + SR_PAD))[t - W4] = ((const float4*)rrow)[t - W4];
    } else {
        int j = t - 2 * W4;                  // 160 spare threads zero the pads
        if (j < SR_PAD / 4) {                // 12 float4 front pad
            ((float4*)sr)[j] = make_float4(0.f, 0.f, 0.f, 0.f);
        } else if (j < SR_PAD / 4 + 4) {     // 4 float4 tail pad
            ((float4*)(sr + SR_PAD + WW))[j - SR_PAD / 4] =
                make_float4(0.f, 0.f, 0.f, 0.f);
        }
    }
    __syncthreads();

    const int bc = row / HH;
    const int h  = row - bc * HH;

    const int w4 = t % W4;                   // fixed output column (float4)
    const int dg = t / W4;                   // disparity group 0..3
    const int d0 = dg * DG;
    const int w0 = w4 * 4;

    const float4 lv = ((const float4*)sl)[w4];

    // Initial right window for d = d0 (aligned: SR_PAD + w0 - d0 is a mult of 4)
    const float4 q = ((const float4*)sr)[(SR_PAD + w0 - d0) >> 2];
    float r0 = q.x, r1 = q.y, r2 = q.z, r3 = q.w;

    float4* out4 = (float4*)out;
    // index (in float4 units) of out[bc, d, h, w4] = ((bc*DISP + d)*HH + h)*W4 + w4
    int oidx = ((bc * DISP + d0) * HH + h) * W4 + w4;

#pragma unroll
    for (int it = 0; it < DG; ++it) {
        const int d = d0 + it;
        float4 o;
        o.x = (w0 + 0 >= d) ? lv.x - r0 : 0.f;
        o.y = (w0 + 1 >= d) ? lv.y - r1 : 0.f;
        o.z = (w0 + 2 >= d) ? lv.z - r2 : 0.f;
        o.w = (w0 + 3 >= d) ? lv.w - r3 : 0.f;
        out4[oidx] = o;
        oidx += HH * W4;

        if (it < DG - 1) {
            // slide the window: r(d+1) = { sr[w0-d-1], r0, r1, r2 }
            const float nr = sr[SR_PAD + w0 - d - 1];
            r3 = r2; r2 = r1; r1 = r0; r0 = nr;
        }
    }
}

extern "C" void kernel_launch(void* const* d_in, const int* in_sizes, int n_in,
                              void* d_out, int out_size) {
    const float* left  = (const float*)d_in[0];
    const float* right = (const float*)d_in[1];
    float* out = (float*)d_out;

    dim3 grid(BB * CC * HH);   // 6144 blocks, one per (b, c, h) row pair
    diffvolume_kernel<<<grid, NTHREADS>>>(left, right, out);
}

// round 3
// speedup vs baseline: 1.1473x; 1.1410x over previous
#include <cuda_runtime.h>

// left, right: [B, C, H, W] fp32 ; out: [B, C, D, H, W] fp32
#define BB 2
#define CC 32
#define HH 96
#define WW 320
#define DISP 48
#define W4 (WW / 4)            // 80 float4 per row
#define NTHREADS 320           // 80 w4-slots x 4 disparity groups
#define DG 12                  // disparities per group (48 / 4)

__global__ __launch_bounds__(NTHREADS)
void diffvolume_kernel(const float* __restrict__ left,
                       const float* __restrict__ right,
                       float* __restrict__ out) {
    const int row = blockIdx.x;              // bc*HH + h
    const int t = threadIdx.x;

    const int w4 = t % W4;                   // fixed output column (float4)
    const int dg = t / W4;                   // disparity group 0..3
    const int d0 = dg * DG;
    const int w0 = w4 * 4;

    const float* lrow = left  + (size_t)row * WW;
    const float* rrow = right + (size_t)row * WW;

    // Left operand: one coalesced float4 load, reused for all 12 disparities.
    const float4 lv = __ldg((const float4*)(lrow + w0));

    // Initial right window for d = d0. If w0 - d0 < 0 the values are garbage,
    // but every output element that would consume them is masked by
    // (w0+k >= d), which is exactly src >= 0. Clamp keeps 16B alignment
    // (w0 and d0 are both multiples of 4).
    int i0 = w0 - d0;
    if (i0 < 0) i0 = 0;
    const float4 q = __ldg((const float4*)(rrow + i0));
    float r0 = q.x, r1 = q.y, r2 = q.z, r3 = q.w;

    const int bc = row / HH;
    const int h  = row - bc * HH;

    float4* out4 = (float4*)out;
    // out[bc, d, h, w4] = ((bc*DISP + d)*HH + h)*W4 + w4
    int oidx = ((bc * DISP + d0) * HH + h) * W4 + w4;

#pragma unroll
    for (int it = 0; it < DG; ++it) {
        const int d = d0 + it;
        float4 o;
        o.x = (w0 + 0 >= d) ? lv.x - r0 : 0.f;
        o.y = (w0 + 1 >= d) ? lv.y - r1 : 0.f;
        o.z = (w0 + 2 >= d) ? lv.z - r2 : 0.f;
        o.w = (w0 + 3 >= d) ? lv.w - r3 : 0.f;
        __stcs(&out4[oidx], o);              // streaming store: no reuse
        oidx += HH * W4;

        if (it < DG - 1) {
            // slide: r(d+1) = { right[w0-d-1], r0, r1, r2 }; clamp -> masked
            int si = w0 - d - 1;
            if (si < 0) si = 0;
            const float nr = __ldg(rrow + si);   // coalesced 128B per warp
            r3 = r2; r2 = r1; r1 = r0; r0 = nr;
        }
    }
}

extern "C" void kernel_launch(void* const* d_in, const int* in_sizes, int n_in,
                              void* d_out, int out_size) {
    const float* left  = (const float*)d_in[0];
    const float* right = (const float*)d_in[1];
    float* out = (float*)d_out;

    dim3 grid(BB * CC * HH);   // 6144 blocks, one per (b, c, h) row pair
    diffvolume_kernel<<<grid, NTHREADS>>>(left, right, out);
}